// round 8
// baseline (speedup 1.0000x reference)
#include <cuda_runtime.h>
#include <math.h>

#define BB 16
#define NN 16384
#define LL 192
#define EE 128
#define DD 128

// scratch (no allocs allowed)
__device__ float g_counts[BB * EE];
__device__ float g_q[EE * DD];
__device__ float g_k[EE * DD];
__device__ float g_v[EE * DD];
__device__ float g_att[EE * EE];

// ---------------------------------------------------------------- counts
__global__ void k_zero_counts() {
    int i = blockIdx.x * blockDim.x + threadIdx.x;
    if (i < BB * EE) g_counts[i] = 0.f;
}

__global__ void k_hist(const int* __restrict__ vidx, const float* __restrict__ mask) {
    __shared__ float h[EE];
    int b = blockIdx.y;
    for (int i = threadIdx.x; i < EE; i += blockDim.x) h[i] = 0.f;
    __syncthreads();
    int n0 = blockIdx.x * blockDim.x + threadIdx.x;
    int stride = gridDim.x * blockDim.x;
    for (int n = n0; n < NN; n += stride) {
        float m = mask[b * NN + n];
        if (m != 0.f) atomicAdd(&h[vidx[b * NN + n]], m);
    }
    __syncthreads();
    for (int i = threadIdx.x; i < EE; i += blockDim.x)
        if (h[i] != 0.f) atomicAdd(&g_counts[b * EE + i], h[i]);
}

// ---------------------------------------------------------------- q,k,v (batch-independent)
__global__ void k_qkv(const float* __restrict__ vhw,
                      const float* __restrict__ Wq, const float* __restrict__ bq,
                      const float* __restrict__ Wk, const float* __restrict__ bk,
                      const float* __restrict__ Wv, const float* __restrict__ bv) {
    __shared__ float vh[DD];
    int e = blockIdx.x;
    int d = threadIdx.x;
    vh[d] = fmaxf(vhw[e * DD + d], 0.f);  // relu(var_hyperedge_w)
    __syncthreads();
    const float *W, *bb;
    float* out;
    if (blockIdx.y == 0)      { W = Wq; bb = bq; out = g_q; }
    else if (blockIdx.y == 1) { W = Wk; bb = bk; out = g_k; }
    else                      { W = Wv; bb = bv; out = g_v; }
    float acc = bb[d];
#pragma unroll 8
    for (int i = 0; i < DD; i++) acc += vh[i] * W[i * DD + d];
    out[e * DD + d] = acc;
}

// ---------------------------------------------------------------- att_base = q k^T / sqrt(D)
__global__ void k_attbase() {
    __shared__ float qr[DD];
    int e = blockIdx.x;
    int f = threadIdx.x;
    qr[f] = g_q[e * DD + f];
    __syncthreads();
    float acc = 0.f;
#pragma unroll 8
    for (int i = 0; i < DD; i++) acc += qr[i] * g_k[f * DD + i];
    g_att[e * EE + f] = acc * 0.08838834764831843f;  // 1/sqrt(128)
}

// ---------------------------------------------------------------- softmax + attn @ v
// grid (8, B): each block handles 16 e-rows of one batch. 128 threads.
__global__ void k_attn_out(const float* __restrict__ thr_p, const float* __restrict__ mc_p,
                           float* __restrict__ outp) {
    int b = blockIdx.y;
    int t = threadIdx.x;
    float thr = *thr_p;
    float mc = *mc_p;
    __shared__ float s_attn[EE];
    __shared__ float red[4];
    int e0 = blockIdx.x * 16;
    for (int e = e0; e < e0 + 16; e++) {
        float a = g_att[e * EE + t];
        if (t == e) {
            float c = g_counts[b * EE + e];
            if (a > thr && c != 0.f) a = (1.f - mc) * a + mc * (c * (1.f / 128.f));
        }
        // block max (4 warps)
        float m = a;
#pragma unroll
        for (int off = 16; off; off >>= 1) m = fmaxf(m, __shfl_xor_sync(0xffffffffu, m, off));
        if ((t & 31) == 0) red[t >> 5] = m;
        __syncthreads();
        m = fmaxf(fmaxf(red[0], red[1]), fmaxf(red[2], red[3]));
        __syncthreads();
        float ex = expf(a - m);
        float s = ex;
#pragma unroll
        for (int off = 16; off; off >>= 1) s += __shfl_xor_sync(0xffffffffu, s, off);
        if ((t & 31) == 0) red[t >> 5] = s;
        __syncthreads();
        s = red[0] + red[1] + red[2] + red[3];
        s_attn[t] = ex / s;
        __syncthreads();
        // out[b,e,d] = sum_f attn[f] * v[f,d]   (t = d)
        float acc = 0.f;
#pragma unroll 8
        for (int f = 0; f < EE; f++) acc += s_attn[f] * g_v[f * DD + t];
        outp[((size_t)(b * EE + e)) * DD + t] = acc;
        __syncthreads();
    }
}

// ---------------------------------------------------------------- obs [B,N,D]
__global__ void k_obs(const float* __restrict__ x, const float* __restrict__ mask,
                      const float* __restrict__ ymask,
                      const float* __restrict__ Wobs, const float* __restrict__ bobs,
                      float* __restrict__ obs) {
    int gid = blockIdx.x * blockDim.x + threadIdx.x;  // 32 threads per node, float4 each
    int node = gid >> 5;
    int d4 = (gid & 31) << 2;
    float xv = x[node];
    float m = mask[node];
    float f1 = 1.f - m + ymask[node];
    float4 w0 = *(const float4*)&Wobs[d4];
    float4 w1 = *(const float4*)&Wobs[DD + d4];
    float4 bb = *(const float4*)&bobs[d4];
    float4 r;
    r.x = fmaxf(fmaf(xv, w0.x, fmaf(f1, w1.x, bb.x)), 0.f) * m;
    r.y = fmaxf(fmaf(xv, w0.y, fmaf(f1, w1.y, bb.y)), 0.f) * m;
    r.z = fmaxf(fmaf(xv, w0.z, fmaf(f1, w1.z, bb.z)), 0.f) * m;
    r.w = fmaxf(fmaf(xv, w0.w, fmaf(f1, w1.w, bb.w)), 0.f) * m;
    __stcs((float4*)&obs[(size_t)node * DD + d4], r);
}

// ---------------------------------------------------------------- temp_he [B,L,D]
__global__ void k_temp(const float* __restrict__ mark, const float* __restrict__ Wt,
                       const float* __restrict__ bt, float* __restrict__ temp) {
    int gid = blockIdx.x * blockDim.x + threadIdx.x;
    if (gid >= BB * LL * DD) return;
    int d = gid & (DD - 1);
    int bl = gid >> 7;
    temp[gid] = sinf(fmaf(mark[bl], Wt[d], bt[d]));
}

// ---------------------------------------------------------------- ti [B,L,N] one-hot
// grid (32, B), 128 threads: each thread owns 4 n's in registers, streams 192 rows.
__global__ void k_ti(const int* __restrict__ tidx, const float* __restrict__ mask,
                     float* __restrict__ ti) {
    int b = blockIdx.y;
    int n = (blockIdx.x * blockDim.x + threadIdx.x) << 2;
    int4 tv = *(const int4*)&tidx[b * NN + n];
    float4 mv = *(const float4*)&mask[b * NN + n];
    float* base = ti + (size_t)b * LL * NN + n;
#pragma unroll 4
    for (int l = 0; l < LL; l++) {
        float4 r;
        r.x = (tv.x == l) ? mv.x : 0.f;
        r.y = (tv.y == l) ? mv.y : 0.f;
        r.z = (tv.z == l) ? mv.z : 0.f;
        r.w = (tv.w == l) ? mv.w : 0.f;
        __stcs((float4*)(base + (size_t)l * NN), r);
    }
}

// ---------------------------------------------------------------- vi [B,E,N] one-hot
__global__ void k_vi(const int* __restrict__ vidx, const float* __restrict__ mask,
                     float* __restrict__ vi) {
    int b = blockIdx.y;
    int n = (blockIdx.x * blockDim.x + threadIdx.x) << 2;
    int4 tv = *(const int4*)&vidx[b * NN + n];
    float4 mv = *(const float4*)&mask[b * NN + n];
    float* base = vi + (size_t)b * EE * NN + n;
#pragma unroll 4
    for (int e = 0; e < EE; e++) {
        float4 r;
        r.x = (tv.x == e) ? mv.x : 0.f;
        r.y = (tv.y == e) ? mv.y : 0.f;
        r.z = (tv.z == e) ? mv.z : 0.f;
        r.w = (tv.w == e) ? mv.w : 0.f;
        __stcs((float4*)(base + (size_t)e * NN), r);
    }
}

// ----------------------------------------------------------------
extern "C" void kernel_launch(void* const* d_in, const int* in_sizes, int n_in,
                              void* d_out, int out_size) {
    const float* x_L   = (const float*)d_in[0];
    const float* mask  = (const float*)d_in[1];
    const float* ymask = (const float*)d_in[2];
    const float* mark  = (const float*)d_in[3];
    const int*   vidx  = (const int*)d_in[4];
    const int*   tidx  = (const int*)d_in[5];
    // N_OBSERVATIONS_MAX may or may not be materialized as a 1-elem input
    int o = (in_sizes[6] == 2 * DD) ? 6 : 7;
    const float* W_obs = (const float*)d_in[o + 0];
    const float* b_obs = (const float*)d_in[o + 1];
    const float* W_t   = (const float*)d_in[o + 2];
    const float* b_t   = (const float*)d_in[o + 3];
    const float* vhw   = (const float*)d_in[o + 4];
    const float* W_q   = (const float*)d_in[o + 5];
    const float* b_q   = (const float*)d_in[o + 6];
    const float* W_k   = (const float*)d_in[o + 7];
    const float* b_k   = (const float*)d_in[o + 8];
    const float* W_v   = (const float*)d_in[o + 9];
    const float* b_v   = (const float*)d_in[o + 10];
    const float* thr   = (const float*)d_in[o + 11];
    const float* mc    = (const float*)d_in[o + 12];

    float* out = (float*)d_out;
    // output layout: obs | temp_he | out | ti | vi
    float* obs_p  = out;
    float* temp_p = obs_p + (size_t)BB * NN * DD;          // 33,554,432
    float* att_p  = temp_p + (size_t)BB * LL * DD;         // +393,216
    float* ti_p   = att_p + (size_t)BB * EE * DD;          // +262,144
    float* vi_p   = ti_p + (size_t)BB * LL * NN;           // +50,331,648

    // small/attention path
    k_zero_counts<<<2, 1024>>>();
    k_hist<<<dim3(16, BB), 256>>>(vidx, mask);
    k_qkv<<<dim3(EE, 3), DD>>>(vhw, W_q, b_q, W_k, b_k, W_v, b_v);
    k_attbase<<<EE, EE>>>();
    k_attn_out<<<dim3(8, BB), 128>>>(thr, mc, att_p);
    // big HBM-bound fills
    k_temp<<<(BB * LL * DD + 255) / 256, 256>>>(mark, W_t, b_t, temp_p);
    k_obs<<<(BB * NN * 32) / 256, 256>>>(x_L, mask, ymask, W_obs, b_obs, obs_p);
    k_ti<<<dim3(NN / 4 / 128, BB), 128>>>(tidx, mask, ti_p);
    k_vi<<<dim3(NN / 4 / 128, BB), 128>>>(vidx, mask, vi_p);
}

// round 11
// speedup vs baseline: 1.0049x; 1.0049x over previous
#include <cuda_runtime.h>
#include <math.h>

#define BB 16
#define NN 16384
#define LL 192
#define EE 128
#define DD 128

// scratch (no allocs allowed)
__device__ float g_counts[BB * EE];
__device__ float g_q[EE * DD];
__device__ float g_k[EE * DD];
__device__ float g_v[EE * DD];
__device__ float g_att[EE * EE];

// ---------------------------------------------------------------- counts
__global__ void k_zero_counts() {
    int i = blockIdx.x * blockDim.x + threadIdx.x;
    if (i < BB * EE) g_counts[i] = 0.f;
}

__global__ void k_hist(const int* __restrict__ vidx, const float* __restrict__ mask) {
    __shared__ float h[EE];
    int b = blockIdx.y;
    for (int i = threadIdx.x; i < EE; i += blockDim.x) h[i] = 0.f;
    __syncthreads();
    int n0 = blockIdx.x * blockDim.x + threadIdx.x;
    int stride = gridDim.x * blockDim.x;
    for (int n = n0; n < NN; n += stride) {
        float m = mask[b * NN + n];
        if (m != 0.f) atomicAdd(&h[vidx[b * NN + n]], m);
    }
    __syncthreads();
    for (int i = threadIdx.x; i < EE; i += blockDim.x)
        if (h[i] != 0.f) atomicAdd(&g_counts[b * EE + i], h[i]);
}

// ---------------------------------------------------------------- q,k,v (batch-independent)
__global__ void k_qkv(const float* __restrict__ vhw,
                      const float* __restrict__ Wq, const float* __restrict__ bq,
                      const float* __restrict__ Wk, const float* __restrict__ bk,
                      const float* __restrict__ Wv, const float* __restrict__ bv) {
    __shared__ float vh[DD];
    int e = blockIdx.x;
    int d = threadIdx.x;
    vh[d] = fmaxf(vhw[e * DD + d], 0.f);  // relu(var_hyperedge_w)
    __syncthreads();
    const float *W, *bb;
    float* out;
    if (blockIdx.y == 0)      { W = Wq; bb = bq; out = g_q; }
    else if (blockIdx.y == 1) { W = Wk; bb = bk; out = g_k; }
    else                      { W = Wv; bb = bv; out = g_v; }
    float acc = bb[d];
#pragma unroll 8
    for (int i = 0; i < DD; i++) acc += vh[i] * W[i * DD + d];
    out[e * DD + d] = acc;
}

// ---------------------------------------------------------------- att_base = q k^T / sqrt(D)
__global__ void k_attbase() {
    __shared__ float qr[DD];
    int e = blockIdx.x;
    int f = threadIdx.x;
    qr[f] = g_q[e * DD + f];
    __syncthreads();
    float acc = 0.f;
#pragma unroll 8
    for (int i = 0; i < DD; i++) acc += qr[i] * g_k[f * DD + i];
    g_att[e * EE + f] = acc * 0.08838834764831843f;  // 1/sqrt(128)
}

// ---------------------------------------------------------------- softmax + attn @ v
// grid (8, B): each block handles 16 e-rows of one batch. 128 threads.
__global__ void k_attn_out(const float* __restrict__ thr_p, const float* __restrict__ mc_p,
                           float* __restrict__ outp) {
    int b = blockIdx.y;
    int t = threadIdx.x;
    float thr = *thr_p;
    float mc = *mc_p;
    __shared__ float s_attn[EE];
    __shared__ float red[4];
    int e0 = blockIdx.x * 16;
    for (int e = e0; e < e0 + 16; e++) {
        float a = g_att[e * EE + t];
        if (t == e) {
            float c = g_counts[b * EE + e];
            if (a > thr && c != 0.f) a = (1.f - mc) * a + mc * (c * (1.f / 128.f));
        }
        // block max (4 warps)
        float m = a;
#pragma unroll
        for (int off = 16; off; off >>= 1) m = fmaxf(m, __shfl_xor_sync(0xffffffffu, m, off));
        if ((t & 31) == 0) red[t >> 5] = m;
        __syncthreads();
        m = fmaxf(fmaxf(red[0], red[1]), fmaxf(red[2], red[3]));
        __syncthreads();
        float ex = expf(a - m);
        float s = ex;
#pragma unroll
        for (int off = 16; off; off >>= 1) s += __shfl_xor_sync(0xffffffffu, s, off);
        if ((t & 31) == 0) red[t >> 5] = s;
        __syncthreads();
        s = red[0] + red[1] + red[2] + red[3];
        s_attn[t] = ex / s;
        __syncthreads();
        // out[b,e,d] = sum_f attn[f] * v[f,d]   (t = d)
        float acc = 0.f;
#pragma unroll 8
        for (int f = 0; f < EE; f++) acc += s_attn[f] * g_v[f * DD + t];
        outp[((size_t)(b * EE + e)) * DD + t] = acc;
        __syncthreads();
    }
}

// ---------------------------------------------------------------- obs [B,N,D]
__global__ void k_obs(const float* __restrict__ x, const float* __restrict__ mask,
                      const float* __restrict__ ymask,
                      const float* __restrict__ Wobs, const float* __restrict__ bobs,
                      float* __restrict__ obs) {
    int gid = blockIdx.x * blockDim.x + threadIdx.x;  // 32 threads per node, float4 each
    int node = gid >> 5;
    int d4 = (gid & 31) << 2;
    float xv = x[node];
    float m = mask[node];
    float f1 = 1.f - m + ymask[node];
    float4 w0 = *(const float4*)&Wobs[d4];
    float4 w1 = *(const float4*)&Wobs[DD + d4];
    float4 bb = *(const float4*)&bobs[d4];
    float4 r;
    r.x = fmaxf(fmaf(xv, w0.x, fmaf(f1, w1.x, bb.x)), 0.f) * m;
    r.y = fmaxf(fmaf(xv, w0.y, fmaf(f1, w1.y, bb.y)), 0.f) * m;
    r.z = fmaxf(fmaf(xv, w0.z, fmaf(f1, w1.z, bb.z)), 0.f) * m;
    r.w = fmaxf(fmaf(xv, w0.w, fmaf(f1, w1.w, bb.w)), 0.f) * m;
    __stcs((float4*)&obs[(size_t)node * DD + d4], r);
}

// ---------------------------------------------------------------- temp_he [B,L,D]
__global__ void k_temp(const float* __restrict__ mark, const float* __restrict__ Wt,
                       const float* __restrict__ bt, float* __restrict__ temp) {
    int gid = blockIdx.x * blockDim.x + threadIdx.x;
    if (gid >= BB * LL * DD) return;
    int d = gid & (DD - 1);
    int bl = gid >> 7;
    temp[gid] = sinf(fmaf(mark[bl], Wt[d], bt[d]));
}

// ---------------------------------------------------------------- ti [B,L,N] one-hot
// grid (32, B), 128 threads: each thread owns 4 n's in registers, streams 192 rows.
__global__ void k_ti(const int* __restrict__ tidx, const float* __restrict__ mask,
                     float* __restrict__ ti) {
    int b = blockIdx.y;
    int n = (blockIdx.x * blockDim.x + threadIdx.x) << 2;
    int4 tv = *(const int4*)&tidx[b * NN + n];
    float4 mv = *(const float4*)&mask[b * NN + n];
    float* base = ti + (size_t)b * LL * NN + n;
#pragma unroll 4
    for (int l = 0; l < LL; l++) {
        float4 r;
        r.x = (tv.x == l) ? mv.x : 0.f;
        r.y = (tv.y == l) ? mv.y : 0.f;
        r.z = (tv.z == l) ? mv.z : 0.f;
        r.w = (tv.w == l) ? mv.w : 0.f;
        __stcs((float4*)(base + (size_t)l * NN), r);
    }
}

// ---------------------------------------------------------------- vi [B,E,N] one-hot
__global__ void k_vi(const int* __restrict__ vidx, const float* __restrict__ mask,
                     float* __restrict__ vi) {
    int b = blockIdx.y;
    int n = (blockIdx.x * blockDim.x + threadIdx.x) << 2;
    int4 tv = *(const int4*)&vidx[b * NN + n];
    float4 mv = *(const float4*)&mask[b * NN + n];
    float* base = vi + (size_t)b * EE * NN + n;
#pragma unroll 4
    for (int e = 0; e < EE; e++) {
        float4 r;
        r.x = (tv.x == e) ? mv.x : 0.f;
        r.y = (tv.y == e) ? mv.y : 0.f;
        r.z = (tv.z == e) ? mv.z : 0.f;
        r.w = (tv.w == e) ? mv.w : 0.f;
        __stcs((float4*)(base + (size_t)e * NN), r);
    }
}

// ----------------------------------------------------------------
extern "C" void kernel_launch(void* const* d_in, const int* in_sizes, int n_in,
                              void* d_out, int out_size) {
    const float* x_L   = (const float*)d_in[0];
    const float* mask  = (const float*)d_in[1];
    const float* ymask = (const float*)d_in[2];
    const float* mark  = (const float*)d_in[3];
    const int*   vidx  = (const int*)d_in[4];
    const int*   tidx  = (const int*)d_in[5];
    // N_OBSERVATIONS_MAX may or may not be materialized as a 1-elem input
    int o = (in_sizes[6] == 2 * DD) ? 6 : 7;
    const float* W_obs = (const float*)d_in[o + 0];
    const float* b_obs = (const float*)d_in[o + 1];
    const float* W_t   = (const float*)d_in[o + 2];
    const float* b_t   = (const float*)d_in[o + 3];
    const float* vhw   = (const float*)d_in[o + 4];
    const float* W_q   = (const float*)d_in[o + 5];
    const float* b_q   = (const float*)d_in[o + 6];
    const float* W_k   = (const float*)d_in[o + 7];
    const float* b_k   = (const float*)d_in[o + 8];
    const float* W_v   = (const float*)d_in[o + 9];
    const float* b_v   = (const float*)d_in[o + 10];
    const float* thr   = (const float*)d_in[o + 11];
    const float* mc    = (const float*)d_in[o + 12];

    float* out = (float*)d_out;
    // output layout: obs | temp_he | out | ti | vi
    float* obs_p  = out;
    float* temp_p = obs_p + (size_t)BB * NN * DD;          // 33,554,432
    float* att_p  = temp_p + (size_t)BB * LL * DD;         // +393,216
    float* ti_p   = att_p + (size_t)BB * EE * DD;          // +262,144
    float* vi_p   = ti_p + (size_t)BB * LL * NN;           // +50,331,648

    // small/attention path
    k_zero_counts<<<2, 1024>>>();
    k_hist<<<dim3(16, BB), 256>>>(vidx, mask);
    k_qkv<<<dim3(EE, 3), DD>>>(vhw, W_q, b_q, W_k, b_k, W_v, b_v);
    k_attbase<<<EE, EE>>>();
    k_attn_out<<<dim3(8, BB), 128>>>(thr, mc, att_p);
    // big HBM-bound fills
    k_temp<<<(BB * LL * DD + 255) / 256, 256>>>(mark, W_t, b_t, temp_p);
    k_obs<<<(BB * NN * 32) / 256, 256>>>(x_L, mask, ymask, W_obs, b_obs, obs_p);
    k_ti<<<dim3(NN / 4 / 128, BB), 128>>>(tidx, mask, ti_p);
    k_vi<<<dim3(NN / 4 / 128, BB), 128>>>(vidx, mask, vi_p);
}

// round 12
// speedup vs baseline: 1.0645x; 1.0593x over previous
#include <cuda_runtime.h>
#include <math.h>

#define BB 16
#define NN 16384
#define LL 192
#define EE 128
#define DD 128

// scratch (no allocs allowed)
__device__ float g_counts[BB * EE];
__device__ float g_q[EE * DD];
__device__ float g_kT[DD * EE];   // K transposed: [d][e]
__device__ float g_v[EE * DD];
__device__ float g_att[EE * EE];

// ---------------------------------------------------------------- side stream (fork/join)
static cudaStream_t g_s2 = nullptr;
static cudaEvent_t g_evF = nullptr, g_evJ = nullptr;
static bool g_ok = false;
namespace {
struct StreamInit {
    StreamInit() {
        g_ok = (cudaStreamCreateWithFlags(&g_s2, cudaStreamNonBlocking) == cudaSuccess) &&
               (cudaEventCreateWithFlags(&g_evF, cudaEventDisableTiming) == cudaSuccess) &&
               (cudaEventCreateWithFlags(&g_evJ, cudaEventDisableTiming) == cudaSuccess);
    }
} s_streamInit;
}

// ---------------------------------------------------------------- counts: one block per batch
__global__ void k_hist(const int* __restrict__ vidx, const float* __restrict__ mask) {
    __shared__ float h[EE];
    int b = blockIdx.x;
    int t = threadIdx.x;
    if (t < EE) h[t] = 0.f;
    __syncthreads();
    for (int n = t; n < NN; n += blockDim.x) {
        float m = mask[b * NN + n];
        if (m != 0.f) atomicAdd(&h[vidx[b * NN + n]], m);
    }
    __syncthreads();
    if (t < EE) g_counts[b * EE + t] = h[t];
}

// ---------------------------------------------------------------- q,kT,v (batch-independent)
__global__ void k_qkv(const float* __restrict__ vhw,
                      const float* __restrict__ Wq, const float* __restrict__ bq,
                      const float* __restrict__ Wk, const float* __restrict__ bk,
                      const float* __restrict__ Wv, const float* __restrict__ bv) {
    __shared__ float vh[DD];
    int e = blockIdx.x;
    int d = threadIdx.x;
    vh[d] = fmaxf(vhw[e * DD + d], 0.f);  // relu(var_hyperedge_w)
    __syncthreads();
    const float *W, *bb;
    if (blockIdx.y == 0)      { W = Wq; bb = bq; }
    else if (blockIdx.y == 1) { W = Wk; bb = bk; }
    else                      { W = Wv; bb = bv; }
    float acc = bb[d];
#pragma unroll 8
    for (int i = 0; i < DD; i++) acc += vh[i] * W[i * DD + d];
    if (blockIdx.y == 0)      g_q[e * DD + d] = acc;
    else if (blockIdx.y == 1) g_kT[d * EE + e] = acc;   // transposed store (cheap, scattered)
    else                      g_v[e * DD + d] = acc;
}

// ---------------------------------------------------------------- att_base = q k^T / sqrt(D)
// coalesced: thread f reads g_kT[i*EE+f]
__global__ void k_attbase() {
    __shared__ float qr[DD];
    int e = blockIdx.x;
    int f = threadIdx.x;
    qr[f] = g_q[e * DD + f];
    __syncthreads();
    float acc = 0.f;
#pragma unroll 8
    for (int i = 0; i < DD; i++) acc += qr[i] * g_kT[i * EE + f];
    g_att[e * EE + f] = acc * 0.08838834764831843f;  // 1/sqrt(128)
}

// ---------------------------------------------------------------- softmax + attn @ v
// grid (8, B): each block handles 16 e-rows of one batch. 128 threads.
__global__ void k_attn_out(const float* __restrict__ thr_p, const float* __restrict__ mc_p,
                           float* __restrict__ outp) {
    int b = blockIdx.y;
    int t = threadIdx.x;
    float thr = *thr_p;
    float mc = *mc_p;
    __shared__ float s_attn[EE];
    __shared__ float red[4];
    int e0 = blockIdx.x * 16;
    for (int e = e0; e < e0 + 16; e++) {
        float a = g_att[e * EE + t];
        if (t == e) {
            float c = g_counts[b * EE + e];
            if (a > thr && c != 0.f) a = (1.f - mc) * a + mc * (c * (1.f / 128.f));
        }
        // block max (4 warps)
        float m = a;
#pragma unroll
        for (int off = 16; off; off >>= 1) m = fmaxf(m, __shfl_xor_sync(0xffffffffu, m, off));
        if ((t & 31) == 0) red[t >> 5] = m;
        __syncthreads();
        m = fmaxf(fmaxf(red[0], red[1]), fmaxf(red[2], red[3]));
        __syncthreads();
        float ex = expf(a - m);
        float s = ex;
#pragma unroll
        for (int off = 16; off; off >>= 1) s += __shfl_xor_sync(0xffffffffu, s, off);
        if ((t & 31) == 0) red[t >> 5] = s;
        __syncthreads();
        s = red[0] + red[1] + red[2] + red[3];
        s_attn[t] = ex / s;
        __syncthreads();
        // out[b,e,d] = sum_f attn[f] * v[f,d]   (t = d, coalesced)
        float acc = 0.f;
#pragma unroll 8
        for (int f = 0; f < EE; f++) acc += s_attn[f] * g_v[f * DD + t];
        outp[((size_t)(b * EE + e)) * DD + t] = acc;
        __syncthreads();
    }
}

// ---------------------------------------------------------------- obs [B,N,D]
__global__ void k_obs(const float* __restrict__ x, const float* __restrict__ mask,
                      const float* __restrict__ ymask,
                      const float* __restrict__ Wobs, const float* __restrict__ bobs,
                      float* __restrict__ obs) {
    int gid = blockIdx.x * blockDim.x + threadIdx.x;  // 32 threads per node, float4 each
    int node = gid >> 5;
    int d4 = (gid & 31) << 2;
    float xv = x[node];
    float m = mask[node];
    float f1 = 1.f - m + ymask[node];
    float4 w0 = *(const float4*)&Wobs[d4];
    float4 w1 = *(const float4*)&Wobs[DD + d4];
    float4 bb = *(const float4*)&bobs[d4];
    float4 r;
    r.x = fmaxf(fmaf(xv, w0.x, fmaf(f1, w1.x, bb.x)), 0.f) * m;
    r.y = fmaxf(fmaf(xv, w0.y, fmaf(f1, w1.y, bb.y)), 0.f) * m;
    r.z = fmaxf(fmaf(xv, w0.z, fmaf(f1, w1.z, bb.z)), 0.f) * m;
    r.w = fmaxf(fmaf(xv, w0.w, fmaf(f1, w1.w, bb.w)), 0.f) * m;
    __stcs((float4*)&obs[(size_t)node * DD + d4], r);
}

// ---------------------------------------------------------------- temp_he [B,L,D]
__global__ void k_temp(const float* __restrict__ mark, const float* __restrict__ Wt,
                       const float* __restrict__ bt, float* __restrict__ temp) {
    int gid = blockIdx.x * blockDim.x + threadIdx.x;
    if (gid >= BB * LL * DD) return;
    int d = gid & (DD - 1);
    int bl = gid >> 7;
    temp[gid] = sinf(fmaf(mark[bl], Wt[d], bt[d]));
}

// ---------------------------------------------------------------- ti [B,L,N] one-hot
__global__ void k_ti(const int* __restrict__ tidx, const float* __restrict__ mask,
                     float* __restrict__ ti) {
    int b = blockIdx.y;
    int n = (blockIdx.x * blockDim.x + threadIdx.x) << 2;
    int4 tv = *(const int4*)&tidx[b * NN + n];
    float4 mv = *(const float4*)&mask[b * NN + n];
    float* base = ti + (size_t)b * LL * NN + n;
#pragma unroll 4
    for (int l = 0; l < LL; l++) {
        float4 r;
        r.x = (tv.x == l) ? mv.x : 0.f;
        r.y = (tv.y == l) ? mv.y : 0.f;
        r.z = (tv.z == l) ? mv.z : 0.f;
        r.w = (tv.w == l) ? mv.w : 0.f;
        __stcs((float4*)(base + (size_t)l * NN), r);
    }
}

// ---------------------------------------------------------------- vi [B,E,N] one-hot
__global__ void k_vi(const int* __restrict__ vidx, const float* __restrict__ mask,
                     float* __restrict__ vi) {
    int b = blockIdx.y;
    int n = (blockIdx.x * blockDim.x + threadIdx.x) << 2;
    int4 tv = *(const int4*)&vidx[b * NN + n];
    float4 mv = *(const float4*)&mask[b * NN + n];
    float* base = vi + (size_t)b * EE * NN + n;
#pragma unroll 4
    for (int e = 0; e < EE; e++) {
        float4 r;
        r.x = (tv.x == e) ? mv.x : 0.f;
        r.y = (tv.y == e) ? mv.y : 0.f;
        r.z = (tv.z == e) ? mv.z : 0.f;
        r.w = (tv.w == e) ? mv.w : 0.f;
        __stcs((float4*)(base + (size_t)e * NN), r);
    }
}

// ----------------------------------------------------------------
extern "C" void kernel_launch(void* const* d_in, const int* in_sizes, int n_in,
                              void* d_out, int out_size) {
    const float* x_L   = (const float*)d_in[0];
    const float* mask  = (const float*)d_in[1];
    const float* ymask = (const float*)d_in[2];
    const float* mark  = (const float*)d_in[3];
    const int*   vidx  = (const int*)d_in[4];
    const int*   tidx  = (const int*)d_in[5];
    // N_OBSERVATIONS_MAX may or may not be materialized as a 1-elem input
    int o = (in_sizes[6] == 2 * DD) ? 6 : 7;
    const float* W_obs = (const float*)d_in[o + 0];
    const float* b_obs = (const float*)d_in[o + 1];
    const float* W_t   = (const float*)d_in[o + 2];
    const float* b_t   = (const float*)d_in[o + 3];
    const float* vhw   = (const float*)d_in[o + 4];
    const float* W_q   = (const float*)d_in[o + 5];
    const float* b_q   = (const float*)d_in[o + 6];
    const float* W_k   = (const float*)d_in[o + 7];
    const float* b_k   = (const float*)d_in[o + 8];
    const float* W_v   = (const float*)d_in[o + 9];
    const float* b_v   = (const float*)d_in[o + 10];
    const float* thr   = (const float*)d_in[o + 11];
    const float* mc    = (const float*)d_in[o + 12];

    float* out = (float*)d_out;
    // output layout: obs | temp_he | out | ti | vi
    float* obs_p  = out;
    float* temp_p = obs_p + (size_t)BB * NN * DD;
    float* att_p  = temp_p + (size_t)BB * LL * DD;
    float* ti_p   = att_p + (size_t)BB * EE * DD;
    float* vi_p   = ti_p + (size_t)BB * LL * NN;

    bool overlap = g_ok;
    cudaStream_t sa = overlap ? g_s2 : (cudaStream_t)0;

    if (overlap) {
        // fork: side stream joins the capture DAG via the fork event
        if (cudaEventRecord(g_evF, 0) != cudaSuccess ||
            cudaStreamWaitEvent(g_s2, g_evF, 0) != cudaSuccess) {
            overlap = false;
            sa = (cudaStream_t)0;
        }
    }

    // attention chain (small, latency-bound) — on side stream when possible
    k_hist<<<BB, 1024, 0, sa>>>(vidx, mask);
    k_qkv<<<dim3(EE, 3), DD, 0, sa>>>(vhw, W_q, b_q, W_k, b_k, W_v, b_v);
    k_attbase<<<EE, EE, 0, sa>>>();
    k_attn_out<<<dim3(8, BB), 128, 0, sa>>>(thr, mc, att_p);
    if (overlap) cudaEventRecord(g_evJ, g_s2);

    // big HBM-bound fills on the main (capture) stream
    k_ti<<<dim3(NN / 4 / 128, BB), 128>>>(tidx, mask, ti_p);
    k_vi<<<dim3(NN / 4 / 128, BB), 128>>>(vidx, mask, vi_p);
    k_obs<<<(BB * NN * 32) / 256, 256>>>(x_L, mask, ymask, W_obs, b_obs, obs_p);
    k_temp<<<(BB * LL * DD + 255) / 256, 256>>>(mark, W_t, b_t, temp_p);

    if (overlap) cudaStreamWaitEvent(0, g_evJ, 0);  // join before capture ends
}

// round 15
// speedup vs baseline: 1.0759x; 1.0107x over previous
#include <cuda_runtime.h>
#include <math.h>

#define BB 16
#define NN 16384
#define LL 192
#define EE 128
#define DD 128

// scratch (no allocs allowed)
__device__ float g_counts[BB * EE];
__device__ float g_q[EE * DD];
__device__ float g_kT[DD * EE];   // K transposed: [d][e]
__device__ float g_v[EE * DD];
__device__ float g_att[EE * EE];

// ---------------------------------------------------------------- side stream (fork/join)
static cudaStream_t g_s2 = nullptr;
static cudaEvent_t g_evF = nullptr, g_evJ = nullptr;
static bool g_ok = false;
namespace {
struct StreamInit {
    StreamInit() {
        g_ok = (cudaStreamCreateWithFlags(&g_s2, cudaStreamNonBlocking) == cudaSuccess) &&
               (cudaEventCreateWithFlags(&g_evF, cudaEventDisableTiming) == cudaSuccess) &&
               (cudaEventCreateWithFlags(&g_evJ, cudaEventDisableTiming) == cudaSuccess);
    }
} s_streamInit;
}

// ---------------------------------------------------------------- counts: one block per batch
__global__ void k_hist(const int* __restrict__ vidx, const float* __restrict__ mask) {
    __shared__ float h[EE];
    int b = blockIdx.x;
    int t = threadIdx.x;
    if (t < EE) h[t] = 0.f;
    __syncthreads();
    for (int n = t; n < NN; n += blockDim.x) {
        float m = mask[b * NN + n];
        if (m != 0.f) atomicAdd(&h[vidx[b * NN + n]], m);
    }
    __syncthreads();
    if (t < EE) g_counts[b * EE + t] = h[t];
}

// ---------------------------------------------------------------- q,kT,v (batch-independent)
__global__ void k_qkv(const float* __restrict__ vhw,
                      const float* __restrict__ Wq, const float* __restrict__ bq,
                      const float* __restrict__ Wk, const float* __restrict__ bk,
                      const float* __restrict__ Wv, const float* __restrict__ bv) {
    __shared__ float vh[DD];
    int e = blockIdx.x;
    int d = threadIdx.x;
    vh[d] = fmaxf(vhw[e * DD + d], 0.f);  // relu(var_hyperedge_w)
    __syncthreads();
    const float *W, *bb;
    if (blockIdx.y == 0)      { W = Wq; bb = bq; }
    else if (blockIdx.y == 1) { W = Wk; bb = bk; }
    else                      { W = Wv; bb = bv; }
    float acc = bb[d];
#pragma unroll 8
    for (int i = 0; i < DD; i++) acc += vh[i] * W[i * DD + d];
    if (blockIdx.y == 0)      g_q[e * DD + d] = acc;
    else if (blockIdx.y == 1) g_kT[d * EE + e] = acc;   // transposed store (cheap, scattered)
    else                      g_v[e * DD + d] = acc;
}

// ---------------------------------------------------------------- att_base = q k^T / sqrt(D)
// coalesced: thread f reads g_kT[i*EE+f]
__global__ void k_attbase() {
    __shared__ float qr[DD];
    int e = blockIdx.x;
    int f = threadIdx.x;
    qr[f] = g_q[e * DD + f];
    __syncthreads();
    float acc = 0.f;
#pragma unroll 8
    for (int i = 0; i < DD; i++) acc += qr[i] * g_kT[i * EE + f];
    g_att[e * EE + f] = acc * 0.08838834764831843f;  // 1/sqrt(128)
}

// ---------------------------------------------------------------- softmax + attn @ v
// grid (8, B): each block handles 16 e-rows of one batch. 128 threads.
__global__ void k_attn_out(const float* __restrict__ thr_p, const float* __restrict__ mc_p,
                           float* __restrict__ outp) {
    int b = blockIdx.y;
    int t = threadIdx.x;
    float thr = *thr_p;
    float mc = *mc_p;
    __shared__ float s_attn[EE];
    __shared__ float red[4];
    int e0 = blockIdx.x * 16;
    for (int e = e0; e < e0 + 16; e++) {
        float a = g_att[e * EE + t];
        if (t == e) {
            float c = g_counts[b * EE + e];
            if (a > thr && c != 0.f) a = (1.f - mc) * a + mc * (c * (1.f / 128.f));
        }
        // block max (4 warps)
        float m = a;
#pragma unroll
        for (int off = 16; off; off >>= 1) m = fmaxf(m, __shfl_xor_sync(0xffffffffu, m, off));
        if ((t & 31) == 0) red[t >> 5] = m;
        __syncthreads();
        m = fmaxf(fmaxf(red[0], red[1]), fmaxf(red[2], red[3]));
        __syncthreads();
        float ex = expf(a - m);
        float s = ex;
#pragma unroll
        for (int off = 16; off; off >>= 1) s += __shfl_xor_sync(0xffffffffu, s, off);
        if ((t & 31) == 0) red[t >> 5] = s;
        __syncthreads();
        s = red[0] + red[1] + red[2] + red[3];
        s_attn[t] = ex / s;
        __syncthreads();
        // out[b,e,d] = sum_f attn[f] * v[f,d]   (t = d, coalesced)
        float acc = 0.f;
#pragma unroll 8
        for (int f = 0; f < EE; f++) acc += s_attn[f] * g_v[f * DD + t];
        outp[((size_t)(b * EE + e)) * DD + t] = acc;
        __syncthreads();
    }
}

// ---------------------------------------------------------------- obs [B,N,D]
__global__ void k_obs(const float* __restrict__ x, const float* __restrict__ mask,
                      const float* __restrict__ ymask,
                      const float* __restrict__ Wobs, const float* __restrict__ bobs,
                      float* __restrict__ obs) {
    int gid = blockIdx.x * blockDim.x + threadIdx.x;  // 32 threads per node, float4 each
    int node = gid >> 5;
    int d4 = (gid & 31) << 2;
    float xv = x[node];
    float m = mask[node];
    float f1 = 1.f - m + ymask[node];
    float4 w0 = *(const float4*)&Wobs[d4];
    float4 w1 = *(const float4*)&Wobs[DD + d4];
    float4 bb = *(const float4*)&bobs[d4];
    float4 r;
    r.x = fmaxf(fmaf(xv, w0.x, fmaf(f1, w1.x, bb.x)), 0.f) * m;
    r.y = fmaxf(fmaf(xv, w0.y, fmaf(f1, w1.y, bb.y)), 0.f) * m;
    r.z = fmaxf(fmaf(xv, w0.z, fmaf(f1, w1.z, bb.z)), 0.f) * m;
    r.w = fmaxf(fmaf(xv, w0.w, fmaf(f1, w1.w, bb.w)), 0.f) * m;
    __stcs((float4*)&obs[(size_t)node * DD + d4], r);
}

// ---------------------------------------------------------------- temp_he [B,L,D]
__global__ void k_temp(const float* __restrict__ mark, const float* __restrict__ Wt,
                       const float* __restrict__ bt, float* __restrict__ temp) {
    int gid = blockIdx.x * blockDim.x + threadIdx.x;
    if (gid >= BB * LL * DD) return;
    int d = gid & (DD - 1);
    int bl = gid >> 7;
    temp[gid] = sinf(fmaf(mark[bl], Wt[d], bt[d]));
}

// ---------------------------------------------------------------- ti [B,L,N] one-hot
__global__ void k_ti(const int* __restrict__ tidx, const float* __restrict__ mask,
                     float* __restrict__ ti) {
    int b = blockIdx.y;
    int n = (blockIdx.x * blockDim.x + threadIdx.x) << 2;
    int4 tv = *(const int4*)&tidx[b * NN + n];
    float4 mv = *(const float4*)&mask[b * NN + n];
    float* base = ti + (size_t)b * LL * NN + n;
#pragma unroll 4
    for (int l = 0; l < LL; l++) {
        float4 r;
        r.x = (tv.x == l) ? mv.x : 0.f;
        r.y = (tv.y == l) ? mv.y : 0.f;
        r.z = (tv.z == l) ? mv.z : 0.f;
        r.w = (tv.w == l) ? mv.w : 0.f;
        __stcs((float4*)(base + (size_t)l * NN), r);
    }
}

// ---------------------------------------------------------------- vi [B,E,N] one-hot
__global__ void k_vi(const int* __restrict__ vidx, const float* __restrict__ mask,
                     float* __restrict__ vi) {
    int b = blockIdx.y;
    int n = (blockIdx.x * blockDim.x + threadIdx.x) << 2;
    int4 tv = *(const int4*)&vidx[b * NN + n];
    float4 mv = *(const float4*)&mask[b * NN + n];
    float* base = vi + (size_t)b * EE * NN + n;
#pragma unroll 4
    for (int e = 0; e < EE; e++) {
        float4 r;
        r.x = (tv.x == e) ? mv.x : 0.f;
        r.y = (tv.y == e) ? mv.y : 0.f;
        r.z = (tv.z == e) ? mv.z : 0.f;
        r.w = (tv.w == e) ? mv.w : 0.f;
        __stcs((float4*)(base + (size_t)e * NN), r);
    }
}

// ----------------------------------------------------------------
extern "C" void kernel_launch(void* const* d_in, const int* in_sizes, int n_in,
                              void* d_out, int out_size) {
    const float* x_L   = (const float*)d_in[0];
    const float* mask  = (const float*)d_in[1];
    const float* ymask = (const float*)d_in[2];
    const float* mark  = (const float*)d_in[3];
    const int*   vidx  = (const int*)d_in[4];
    const int*   tidx  = (const int*)d_in[5];
    // N_OBSERVATIONS_MAX may or may not be materialized as a 1-elem input
    int o = (in_sizes[6] == 2 * DD) ? 6 : 7;
    const float* W_obs = (const float*)d_in[o + 0];
    const float* b_obs = (const float*)d_in[o + 1];
    const float* W_t   = (const float*)d_in[o + 2];
    const float* b_t   = (const float*)d_in[o + 3];
    const float* vhw   = (const float*)d_in[o + 4];
    const float* W_q   = (const float*)d_in[o + 5];
    const float* b_q   = (const float*)d_in[o + 6];
    const float* W_k   = (const float*)d_in[o + 7];
    const float* b_k   = (const float*)d_in[o + 8];
    const float* W_v   = (const float*)d_in[o + 9];
    const float* b_v   = (const float*)d_in[o + 10];
    const float* thr   = (const float*)d_in[o + 11];
    const float* mc    = (const float*)d_in[o + 12];

    float* out = (float*)d_out;
    // output layout: obs | temp_he | out | ti | vi
    float* obs_p  = out;
    float* temp_p = obs_p + (size_t)BB * NN * DD;
    float* att_p  = temp_p + (size_t)BB * LL * DD;
    float* ti_p   = att_p + (size_t)BB * EE * DD;
    float* vi_p   = ti_p + (size_t)BB * LL * NN;

    bool overlap = g_ok;
    cudaStream_t sa = overlap ? g_s2 : (cudaStream_t)0;

    if (overlap) {
        // fork: side stream joins the capture DAG via the fork event
        if (cudaEventRecord(g_evF, 0) != cudaSuccess ||
            cudaStreamWaitEvent(g_s2, g_evF, 0) != cudaSuccess) {
            overlap = false;
            sa = (cudaStream_t)0;
        }
    }

    // attention chain (small, latency-bound) — on side stream when possible
    k_hist<<<BB, 1024, 0, sa>>>(vidx, mask);
    k_qkv<<<dim3(EE, 3), DD, 0, sa>>>(vhw, W_q, b_q, W_k, b_k, W_v, b_v);
    k_attbase<<<EE, EE, 0, sa>>>();
    k_attn_out<<<dim3(8, BB), 128, 0, sa>>>(thr, mc, att_p);
    if (overlap) cudaEventRecord(g_evJ, g_s2);

    // big HBM-bound fills on the main (capture) stream
    k_ti<<<dim3(NN / 4 / 128, BB), 128>>>(tidx, mask, ti_p);
    k_vi<<<dim3(NN / 4 / 128, BB), 128>>>(vidx, mask, vi_p);
    k_obs<<<(BB * NN * 32) / 256, 256>>>(x_L, mask, ymask, W_obs, b_obs, obs_p);
    k_temp<<<(BB * LL * DD + 255) / 256, 256>>>(mark, W_t, b_t, temp_p);

    if (overlap) cudaStreamWaitEvent(0, g_evJ, 0);  // join before capture ends
}